// round 13
// baseline (speedup 1.0000x reference)
#include <cuda_runtime.h>
#include <math.h>

#define BB      16
#define HWN     589824            // 768*768
#define KBINS   8192              // 2^13 bins; counters = 1 MB, L2-resident
#define KH      (KBINS / 2)       // packed u16-pair words per histogram
#define HBLK    18                // hist blocks per sample
#define HTH     1024
#define EPB     (HWN / HBLK)      // 32768 elements per block (u16-safe: <= 32768 < 65536)
#define HITER   (EPB / (HTH * 4)) // 8 float4 iterations per thread
#define EVENTS  (2 * KBINS)       // merged CDF events per sample (16384)
#define MTH     512
#define MEPT    2
#define MSLICES (EVENTS / (MTH * MEPT))   // 16 merge blocks per sample -> 256 total

// Scratch (allocation-free rule: __device__ globals)
__device__ unsigned int       g_cnt[2][BB][KBINS];   // hist -> CDF in place
__device__ unsigned long long g_acc;
__device__ unsigned int       g_done = 0;

// ---------------------------------------------------------------------------
// 1) sigmoid(x1-x0) + SMEM-privatized histograms (u16-packed), flush as u64 REDs
// ---------------------------------------------------------------------------
__global__ void __launch_bounds__(HTH, 2)
hist_kernel(const float* __restrict__ x, const float* __restrict__ t) {
    __shared__ unsigned int sp[KH];
    __shared__ unsigned int sq[KH];

    const int tid = threadIdx.x;
    const int b   = blockIdx.y;

    if (blockIdx.x == 0 && b == 0 && tid == 0) g_acc = 0ull;

    for (int i = tid; i < KH; i += HTH) { sp[i] = 0u; sq[i] = 0u; }
    __syncthreads();

    const size_t off = (size_t)blockIdx.x * EPB;
    const float* __restrict__ x0p = x + (size_t)b * 2 * HWN + off;
    const float* __restrict__ x1p = x0p + HWN;
    const float* __restrict__ tp  = t + (size_t)b * HWN + off;
    const float kf = (float)KBINS;

    #pragma unroll
    for (int it = 0; it < HITER; ++it) {
        int i4 = (it * HTH + tid) * 4;
        float4 a0 = *reinterpret_cast<const float4*>(&x0p[i4]);
        float4 a1 = *reinterpret_cast<const float4*>(&x1p[i4]);
        float4 tv = *reinterpret_cast<const float4*>(&tp[i4]);
        #pragma unroll
        for (int j = 0; j < 4; ++j) {
            float d  = (j == 0 ? a0.x - a1.x : j == 1 ? a0.y - a1.y : j == 2 ? a0.z - a1.z : a0.w - a1.w);
            float v  = __fdividef(1.0f, 1.0f + __expf(d));
            int bp = (int)(v * kf);
            bp = bp > KBINS - 1 ? KBINS - 1 : bp;            // sigmoid > 0: no lower clamp
            atomicAdd(&sp[bp >> 1], 1u << ((bp & 1) << 4));
            float tj = (j == 0 ? tv.x : j == 1 ? tv.y : j == 2 ? tv.z : tv.w);
            int bq = (int)(tj * kf);
            bq = bq > KBINS - 1 ? KBINS - 1 : bq;            // t >= 0: no lower clamp
            atomicAdd(&sq[bq >> 1], 1u << ((bq & 1) << 4));
        }
    }
    __syncthreads();

    unsigned long long* __restrict__ gp = reinterpret_cast<unsigned long long*>(&g_cnt[0][b][0]);
    unsigned long long* __restrict__ gq = reinterpret_cast<unsigned long long*>(&g_cnt[1][b][0]);
    for (int w = tid; w < KH; w += HTH) {
        unsigned v = sp[w];
        if (v) atomicAdd(&gp[w], (unsigned long long)(v & 0xFFFFu) |
                                 ((unsigned long long)(v >> 16) << 32));
        v = sq[w];
        if (v) atomicAdd(&gq[w], (unsigned long long)(v & 0xFFFFu) |
                                 ((unsigned long long)(v >> 16) << 32));
    }
}

// ---------------------------------------------------------------------------
// 2) one block scans one (array, sample) row of 8192 counters in place (L2)
// ---------------------------------------------------------------------------
__global__ void scan_rows() {
    __shared__ unsigned int warpsums[32];
    unsigned int* row = &g_cnt[blockIdx.y][blockIdx.x][0];
    int tbase = threadIdx.x * 8;

    uint4 v0 = *reinterpret_cast<uint4*>(&row[tbase + 0]);
    uint4 v1 = *reinterpret_cast<uint4*>(&row[tbase + 4]);

    v0.y += v0.x; v0.z += v0.y; v0.w += v0.z;
    v1.x += v0.w; v1.y += v1.x; v1.z += v1.y; v1.w += v1.z;
    unsigned tot = v1.w;

    unsigned lane = threadIdx.x & 31, wid = threadIdx.x >> 5;
    unsigned s = tot;
    #pragma unroll
    for (int o = 1; o < 32; o <<= 1) {
        unsigned n = __shfl_up_sync(0xFFFFFFFFu, s, o);
        if (lane >= o) s += n;
    }
    if (lane == 31) warpsums[wid] = s;
    __syncthreads();
    if (wid == 0) {
        unsigned ws = warpsums[lane];
        #pragma unroll
        for (int o = 1; o < 32; o <<= 1) {
            unsigned n = __shfl_up_sync(0xFFFFFFFFu, ws, o);
            if (lane >= o) ws += n;
        }
        warpsums[lane] = ws;
    }
    __syncthreads();

    unsigned prefix = (s - tot) + (wid ? warpsums[wid - 1] : 0u);
    v0.x += prefix; v0.y += prefix; v0.z += prefix; v0.w += prefix;
    v1.x += prefix; v1.y += prefix; v1.z += prefix; v1.w += prefix;

    *reinterpret_cast<uint4*>(&row[tbase + 0]) = v0;
    *reinterpret_cast<uint4*>(&row[tbase + 4]) = v1;
}

// ---------------------------------------------------------------------------
// 3) merged-event sum straight from L2-resident CDFs + ticket finalize
// ---------------------------------------------------------------------------
__device__ __forceinline__ unsigned long long warpReduceU64(unsigned long long v) {
    #pragma unroll
    for (int o = 16; o > 0; o >>= 1) v += __shfl_down_sync(0xFFFFFFFFu, v, o);
    return v;
}

__global__ void __launch_bounds__(MTH)
merge_kernel(float* __restrict__ out) {
    const int b   = blockIdx.y;
    const int tid = threadIdx.x;
    const unsigned* __restrict__ sp = g_cnt[0][b];
    const unsigned* __restrict__ sq = g_cnt[1][b];

    const int i0 = (blockIdx.x * MTH + tid) * MEPT;

    // merge-path diagonal search: smallest a with (b==0 || a==KBINS || sq[b-1] < sp[a])
    int lo = i0 - KBINS; lo = lo < 0 ? 0 : lo;
    int hi = i0 < KBINS ? i0 : KBINS;
    while (lo < hi) {
        int a = (lo + hi) >> 1;
        int bq = i0 - a;
        if (bq > 0 && a < KBINS && __ldg(&sq[bq - 1]) >= __ldg(&sp[a])) lo = a + 1;
        else hi = a;
    }
    int a = lo, bq = i0 - lo;

    unsigned long long local = 0ull;
    #pragma unroll
    for (int e = 0; e < MEPT; ++e) {
        unsigned vp = (a  < KBINS) ? __ldg(&sp[a])  : 0xFFFFFFFFu;
        unsigned vq = (bq < KBINS) ? __ldg(&sq[bq]) : 0xFFFFFFFFu;
        unsigned vcur;
        if (vp <= vq) { vcur = vp; ++a; } else { vcur = vq; ++bq; }
        unsigned np = (a  < KBINS) ? __ldg(&sp[a])  : 0xFFFFFFFFu;
        unsigned nq = (bq < KBINS) ? __ldg(&sq[bq]) : 0xFFFFFFFFu;
        unsigned vnext = np < nq ? np : nq;
        if (vnext != 0xFFFFFFFFu) {
            int dk = a - bq;
            local += (unsigned long long)(vnext - vcur) * (unsigned long long)(dk * dk);
        }
    }

    local = warpReduceU64(local);
    __shared__ unsigned long long shred[MTH / 32];
    int lane = tid & 31, wid = tid >> 5;
    if (lane == 0) shred[wid] = local;
    __syncthreads();
    if (wid == 0) {
        unsigned long long v = (lane < (MTH >> 5)) ? shred[lane] : 0ull;
        v = warpReduceU64(v);
        if (lane == 0) {
            atomicAdd(&g_acc, v);
            __threadfence();
            unsigned old = atomicAdd(&g_done, 1u);
            if (old == BB * MSLICES - 1) {            // last block finalizes
                g_done = 0;                           // self-reset for graph replay
                unsigned long long total = *(volatile unsigned long long*)&g_acc;
                const double ds = 1.0 / (double)KBINS;
                out[0] = (float)((double)total * ds * ds / ((double)BB * (double)HWN));
            }
        }
    }
}

// ---------------------------------------------------------------------------
extern "C" void kernel_launch(void* const* d_in, const int* in_sizes, int n_in,
                              void* d_out, int out_size) {
    const float* x = (const float*)d_in[0];   // [16, 2, 768, 768]
    const float* t = (const float*)d_in[1];   // [16, 768, 768]
    float* out = (float*)d_out;               // scalar

    void* cnt_ptr = nullptr;
    cudaGetSymbolAddress(&cnt_ptr, g_cnt);
    cudaMemsetAsync(cnt_ptr, 0, sizeof(unsigned int) * 2 * BB * KBINS, 0);

    hist_kernel<<<dim3(HBLK, BB), HTH>>>(x, t);
    scan_rows<<<dim3(BB, 2), 1024>>>();
    merge_kernel<<<dim3(MSLICES, BB), MTH>>>(out);
}

// round 14
// speedup vs baseline: 1.1565x; 1.1565x over previous
#include <cuda_runtime.h>
#include <math.h>

#define BB      16
#define HWN     589824            // 768*768
#define KBINS   8192              // 2^13 bins; counters = 1 MB, L2-resident
#define KH      (KBINS / 2)       // packed u16-pair words per histogram
#define HBLK    36                // hist blocks per sample (best-known R9 config)
#define HTH     512
#define EPB     (HWN / HBLK)      // 16384 elements per block (u16-safe)
#define HITER   (EPB / (HTH * 4)) // 8 float4 iterations per thread
#define EVENTS  (2 * KBINS)       // merged CDF events per sample (16384)
#define MTH     512
#define MEPT    2
#define MSLICES (EVENTS / (MTH * MEPT))   // 16 merge blocks per sample -> 256 total

// Scratch (allocation-free rule: __device__ globals).
// g_cnt starts zeroed (static init) and every merge launch re-zeroes it,
// so no memset is ever needed — the pipeline is self-cleaning across replays.
__device__ unsigned int       g_cnt[2][BB][KBINS];   // hist -> CDF in place
__device__ unsigned long long g_acc;
__device__ unsigned int       g_done = 0;
__device__ unsigned int       g_done_s[BB];          // per-sample merge tickets

// ---------------------------------------------------------------------------
// 1) sigmoid(x1-x0) + SMEM-privatized histograms (u16-packed), flush as u64 REDs
// ---------------------------------------------------------------------------
__global__ void __launch_bounds__(HTH, 4)
hist_kernel(const float* __restrict__ x, const float* __restrict__ t) {
    __shared__ unsigned int sp[KH];
    __shared__ unsigned int sq[KH];

    const int tid = threadIdx.x;
    const int b   = blockIdx.y;

    if (blockIdx.x == 0 && b == 0 && tid == 0) g_acc = 0ull;

    for (int i = tid; i < KH; i += HTH) { sp[i] = 0u; sq[i] = 0u; }
    __syncthreads();

    const size_t off = (size_t)blockIdx.x * EPB;
    const float* __restrict__ x0p = x + (size_t)b * 2 * HWN + off;
    const float* __restrict__ x1p = x0p + HWN;
    const float* __restrict__ tp  = t + (size_t)b * HWN + off;
    const float kf = (float)KBINS;

    #pragma unroll
    for (int it = 0; it < HITER; ++it) {
        int i4 = (it * HTH + tid) * 4;
        float4 a0 = *reinterpret_cast<const float4*>(&x0p[i4]);
        float4 a1 = *reinterpret_cast<const float4*>(&x1p[i4]);
        float4 tv = *reinterpret_cast<const float4*>(&tp[i4]);
        #pragma unroll
        for (int j = 0; j < 4; ++j) {
            float d  = (j == 0 ? a0.x - a1.x : j == 1 ? a0.y - a1.y : j == 2 ? a0.z - a1.z : a0.w - a1.w);
            float v  = __fdividef(1.0f, 1.0f + __expf(d));
            int bp = (int)(v * kf);
            bp = bp > KBINS - 1 ? KBINS - 1 : bp;            // sigmoid > 0: no lower clamp
            atomicAdd(&sp[bp >> 1], 1u << ((bp & 1) << 4));
            float tj = (j == 0 ? tv.x : j == 1 ? tv.y : j == 2 ? tv.z : tv.w);
            int bq = (int)(tj * kf);
            bq = bq > KBINS - 1 ? KBINS - 1 : bq;            // t >= 0: no lower clamp
            atomicAdd(&sq[bq >> 1], 1u << ((bq & 1) << 4));
        }
    }
    __syncthreads();

    unsigned long long* __restrict__ gp = reinterpret_cast<unsigned long long*>(&g_cnt[0][b][0]);
    unsigned long long* __restrict__ gq = reinterpret_cast<unsigned long long*>(&g_cnt[1][b][0]);
    for (int w = tid; w < KH; w += HTH) {
        unsigned v = sp[w];
        if (v) atomicAdd(&gp[w], (unsigned long long)(v & 0xFFFFu) |
                                 ((unsigned long long)(v >> 16) << 32));
        v = sq[w];
        if (v) atomicAdd(&gq[w], (unsigned long long)(v & 0xFFFFu) |
                                 ((unsigned long long)(v >> 16) << 32));
    }
}

// ---------------------------------------------------------------------------
// 2) one block scans one (array, sample) row of 8192 counters in place (L2)
// ---------------------------------------------------------------------------
__global__ void scan_rows() {
    __shared__ unsigned int warpsums[32];
    unsigned int* row = &g_cnt[blockIdx.y][blockIdx.x][0];
    int tbase = threadIdx.x * 8;

    uint4 v0 = *reinterpret_cast<uint4*>(&row[tbase + 0]);
    uint4 v1 = *reinterpret_cast<uint4*>(&row[tbase + 4]);

    v0.y += v0.x; v0.z += v0.y; v0.w += v0.z;
    v1.x += v0.w; v1.y += v1.x; v1.z += v1.y; v1.w += v1.z;
    unsigned tot = v1.w;

    unsigned lane = threadIdx.x & 31, wid = threadIdx.x >> 5;
    unsigned s = tot;
    #pragma unroll
    for (int o = 1; o < 32; o <<= 1) {
        unsigned n = __shfl_up_sync(0xFFFFFFFFu, s, o);
        if (lane >= o) s += n;
    }
    if (lane == 31) warpsums[wid] = s;
    __syncthreads();
    if (wid == 0) {
        unsigned ws = warpsums[lane];
        #pragma unroll
        for (int o = 1; o < 32; o <<= 1) {
            unsigned n = __shfl_up_sync(0xFFFFFFFFu, ws, o);
            if (lane >= o) ws += n;
        }
        warpsums[lane] = ws;
    }
    __syncthreads();

    unsigned prefix = (s - tot) + (wid ? warpsums[wid - 1] : 0u);
    v0.x += prefix; v0.y += prefix; v0.z += prefix; v0.w += prefix;
    v1.x += prefix; v1.y += prefix; v1.z += prefix; v1.w += prefix;

    *reinterpret_cast<uint4*>(&row[tbase + 0]) = v0;
    *reinterpret_cast<uint4*>(&row[tbase + 4]) = v1;
}

// ---------------------------------------------------------------------------
// 3) merged-event sum from L2-resident CDFs + self-cleaning + ticket finalize
// ---------------------------------------------------------------------------
__device__ __forceinline__ unsigned long long warpReduceU64(unsigned long long v) {
    #pragma unroll
    for (int o = 16; o > 0; o >>= 1) v += __shfl_down_sync(0xFFFFFFFFu, v, o);
    return v;
}

__global__ void __launch_bounds__(MTH)
merge_kernel(float* __restrict__ out) {
    const int b   = blockIdx.y;
    const int tid = threadIdx.x;
    const unsigned* __restrict__ sp = g_cnt[0][b];
    const unsigned* __restrict__ sq = g_cnt[1][b];

    const int i0 = (blockIdx.x * MTH + tid) * MEPT;

    // merge-path diagonal search: smallest a with (b==0 || a==KBINS || sq[b-1] < sp[a])
    int lo = i0 - KBINS; lo = lo < 0 ? 0 : lo;
    int hi = i0 < KBINS ? i0 : KBINS;
    while (lo < hi) {
        int a = (lo + hi) >> 1;
        int bq = i0 - a;
        if (bq > 0 && a < KBINS && __ldg(&sq[bq - 1]) >= __ldg(&sp[a])) lo = a + 1;
        else hi = a;
    }
    int a = lo, bq = i0 - lo;

    unsigned long long local = 0ull;
    #pragma unroll
    for (int e = 0; e < MEPT; ++e) {
        unsigned vp = (a  < KBINS) ? __ldg(&sp[a])  : 0xFFFFFFFFu;
        unsigned vq = (bq < KBINS) ? __ldg(&sq[bq]) : 0xFFFFFFFFu;
        unsigned vcur;
        if (vp <= vq) { vcur = vp; ++a; } else { vcur = vq; ++bq; }
        unsigned np = (a  < KBINS) ? __ldg(&sp[a])  : 0xFFFFFFFFu;
        unsigned nq = (bq < KBINS) ? __ldg(&sq[bq]) : 0xFFFFFFFFu;
        unsigned vnext = np < nq ? np : nq;
        if (vnext != 0xFFFFFFFFu) {
            int dk = a - bq;
            local += (unsigned long long)(vnext - vcur) * (unsigned long long)(dk * dk);
        }
    }

    local = warpReduceU64(local);
    __shared__ unsigned long long shred[MTH / 32];
    __shared__ int do_zero;
    int lane = tid & 31, wid = tid >> 5;
    if (lane == 0) shred[wid] = local;
    __syncthreads();
    if (wid == 0) {
        unsigned long long v = (lane < (MTH >> 5)) ? shred[lane] : 0ull;
        v = warpReduceU64(v);
        if (lane == 0) {
            atomicAdd(&g_acc, v);
            __threadfence();
            // per-sample ticket: last merge block of sample b cleans its rows
            unsigned olds = atomicAdd(&g_done_s[b], 1u);
            do_zero = (olds == MSLICES - 1);
            if (do_zero) g_done_s[b] = 0;            // self-reset for graph replay
            // global ticket: last of all 256 blocks finalizes
            unsigned old = atomicAdd(&g_done, 1u);
            if (old == BB * MSLICES - 1) {
                g_done = 0;                           // self-reset for graph replay
                unsigned long long total = *(volatile unsigned long long*)&g_acc;
                const double ds = 1.0 / (double)KBINS;
                out[0] = (float)((double)total * ds * ds / ((double)BB * (double)HWN));
            }
        }
    }
    __syncthreads();
    if (do_zero) {
        // all readers of sample b's rows have arrived (ticket) -> safe to zero.
        // 2 rows x 8192 u32 = 64 KB, 512 threads x 8 uint4 stores.
        uint4 z = make_uint4(0u, 0u, 0u, 0u);
        uint4* r0 = reinterpret_cast<uint4*>(&g_cnt[0][b][0]);
        uint4* r1 = reinterpret_cast<uint4*>(&g_cnt[1][b][0]);
        #pragma unroll
        for (int i = 0; i < KBINS / 4 / MTH; ++i) {
            r0[i * MTH + tid] = z;
            r1[i * MTH + tid] = z;
        }
    }
}

// ---------------------------------------------------------------------------
extern "C" void kernel_launch(void* const* d_in, const int* in_sizes, int n_in,
                              void* d_out, int out_size) {
    const float* x = (const float*)d_in[0];   // [16, 2, 768, 768]
    const float* t = (const float*)d_in[1];   // [16, 768, 768]
    float* out = (float*)d_out;               // scalar

    hist_kernel<<<dim3(HBLK, BB), HTH>>>(x, t);
    scan_rows<<<dim3(BB, 2), 1024>>>();
    merge_kernel<<<dim3(MSLICES, BB), MTH>>>(out);
}

// round 15
// speedup vs baseline: 1.3949x; 1.2062x over previous
#include <cuda_runtime.h>
#include <math.h>

#define BB      16
#define HWN     589824            // 768*768
#define KBINS   4096              // 2^12 bins; counters = 512 KB, L2-resident
#define KH      (KBINS / 2)       // packed u16-pair words per histogram
#define HBLK    36                // hist blocks per sample
#define HTH     512
#define EPB     (HWN / HBLK)      // 16384 elements per block (u16-safe)
#define HITER   (EPB / (HTH * 4)) // 8 float4 iterations per thread
#define EVENTS  (2 * KBINS)       // merged CDF events per sample (8192)
#define MTH     512
#define MEPT    2
#define MSLICES (EVENTS / (MTH * MEPT))   // 8 merge blocks per sample -> 128 total

// Scratch (allocation-free rule: __device__ globals)
__device__ unsigned int       g_cnt[2][BB][KBINS];   // hist -> CDF in place
__device__ unsigned long long g_acc;
__device__ unsigned int       g_done = 0;

// ---------------------------------------------------------------------------
// 1) sigmoid(x1-x0) + SMEM-privatized histograms (u16-packed), flush as u64 REDs
// ---------------------------------------------------------------------------
__global__ void __launch_bounds__(HTH, 4)
hist_kernel(const float* __restrict__ x, const float* __restrict__ t) {
    __shared__ unsigned int sp[KH];
    __shared__ unsigned int sq[KH];

    const int tid = threadIdx.x;
    const int b   = blockIdx.y;

    if (blockIdx.x == 0 && b == 0 && tid == 0) g_acc = 0ull;

    for (int i = tid; i < KH; i += HTH) { sp[i] = 0u; sq[i] = 0u; }
    __syncthreads();

    const size_t off = (size_t)blockIdx.x * EPB;
    const float* __restrict__ x0p = x + (size_t)b * 2 * HWN + off;
    const float* __restrict__ x1p = x0p + HWN;
    const float* __restrict__ tp  = t + (size_t)b * HWN + off;
    const float kf = (float)KBINS;

    #pragma unroll
    for (int it = 0; it < HITER; ++it) {
        int i4 = (it * HTH + tid) * 4;
        float4 a0 = *reinterpret_cast<const float4*>(&x0p[i4]);
        float4 a1 = *reinterpret_cast<const float4*>(&x1p[i4]);
        float4 tv = *reinterpret_cast<const float4*>(&tp[i4]);
        #pragma unroll
        for (int j = 0; j < 4; ++j) {
            float d  = (j == 0 ? a0.x - a1.x : j == 1 ? a0.y - a1.y : j == 2 ? a0.z - a1.z : a0.w - a1.w);
            float v  = __fdividef(1.0f, 1.0f + __expf(d));
            int bp = (int)(v * kf);
            bp = bp > KBINS - 1 ? KBINS - 1 : bp;            // sigmoid > 0: no lower clamp
            atomicAdd(&sp[bp >> 1], 1u << ((bp & 1) << 4));
            float tj = (j == 0 ? tv.x : j == 1 ? tv.y : j == 2 ? tv.z : tv.w);
            int bq = (int)(tj * kf);
            bq = bq > KBINS - 1 ? KBINS - 1 : bq;            // t >= 0: no lower clamp
            atomicAdd(&sq[bq >> 1], 1u << ((bq & 1) << 4));
        }
    }
    __syncthreads();

    unsigned long long* __restrict__ gp = reinterpret_cast<unsigned long long*>(&g_cnt[0][b][0]);
    unsigned long long* __restrict__ gq = reinterpret_cast<unsigned long long*>(&g_cnt[1][b][0]);
    for (int w = tid; w < KH; w += HTH) {
        unsigned v = sp[w];
        if (v) atomicAdd(&gp[w], (unsigned long long)(v & 0xFFFFu) |
                                 ((unsigned long long)(v >> 16) << 32));
        v = sq[w];
        if (v) atomicAdd(&gq[w], (unsigned long long)(v & 0xFFFFu) |
                                 ((unsigned long long)(v >> 16) << 32));
    }
}

// ---------------------------------------------------------------------------
// 2) one block scans one (array, sample) row of 4096 counters in place (L2)
// ---------------------------------------------------------------------------
__global__ void scan_rows() {
    __shared__ unsigned int warpsums[32];
    unsigned int* row = &g_cnt[blockIdx.y][blockIdx.x][0];
    int tbase = threadIdx.x * 4;

    uint4 v0 = *reinterpret_cast<uint4*>(&row[tbase]);
    v0.y += v0.x; v0.z += v0.y; v0.w += v0.z;
    unsigned tot = v0.w;

    unsigned lane = threadIdx.x & 31, wid = threadIdx.x >> 5;
    unsigned s = tot;
    #pragma unroll
    for (int o = 1; o < 32; o <<= 1) {
        unsigned n = __shfl_up_sync(0xFFFFFFFFu, s, o);
        if (lane >= o) s += n;
    }
    if (lane == 31) warpsums[wid] = s;
    __syncthreads();
    if (wid == 0) {
        unsigned ws = warpsums[lane];
        #pragma unroll
        for (int o = 1; o < 32; o <<= 1) {
            unsigned n = __shfl_up_sync(0xFFFFFFFFu, ws, o);
            if (lane >= o) ws += n;
        }
        warpsums[lane] = ws;
    }
    __syncthreads();

    unsigned prefix = (s - tot) + (wid ? warpsums[wid - 1] : 0u);
    v0.x += prefix; v0.y += prefix; v0.z += prefix; v0.w += prefix;
    *reinterpret_cast<uint4*>(&row[tbase]) = v0;
}

// ---------------------------------------------------------------------------
// 3) merged-event sum straight from L2-resident CDFs + ticket finalize
// ---------------------------------------------------------------------------
__device__ __forceinline__ unsigned long long warpReduceU64(unsigned long long v) {
    #pragma unroll
    for (int o = 16; o > 0; o >>= 1) v += __shfl_down_sync(0xFFFFFFFFu, v, o);
    return v;
}

__global__ void __launch_bounds__(MTH)
merge_kernel(float* __restrict__ out) {
    const int b   = blockIdx.y;
    const int tid = threadIdx.x;
    const unsigned* __restrict__ sp = g_cnt[0][b];
    const unsigned* __restrict__ sq = g_cnt[1][b];

    const int i0 = (blockIdx.x * MTH + tid) * MEPT;

    // merge-path diagonal search: smallest a with (b==0 || a==KBINS || sq[b-1] < sp[a])
    int lo = i0 - KBINS; lo = lo < 0 ? 0 : lo;
    int hi = i0 < KBINS ? i0 : KBINS;
    while (lo < hi) {
        int a = (lo + hi) >> 1;
        int bq = i0 - a;
        if (bq > 0 && a < KBINS && __ldg(&sq[bq - 1]) >= __ldg(&sp[a])) lo = a + 1;
        else hi = a;
    }
    int a = lo, bq = i0 - lo;

    unsigned long long local = 0ull;
    #pragma unroll
    for (int e = 0; e < MEPT; ++e) {
        unsigned vp = (a  < KBINS) ? __ldg(&sp[a])  : 0xFFFFFFFFu;
        unsigned vq = (bq < KBINS) ? __ldg(&sq[bq]) : 0xFFFFFFFFu;
        unsigned vcur;
        if (vp <= vq) { vcur = vp; ++a; } else { vcur = vq; ++bq; }
        unsigned np = (a  < KBINS) ? __ldg(&sp[a])  : 0xFFFFFFFFu;
        unsigned nq = (bq < KBINS) ? __ldg(&sq[bq]) : 0xFFFFFFFFu;
        unsigned vnext = np < nq ? np : nq;
        if (vnext != 0xFFFFFFFFu) {
            int dk = a - bq;
            local += (unsigned long long)(vnext - vcur) * (unsigned long long)(dk * dk);
        }
    }

    local = warpReduceU64(local);
    __shared__ unsigned long long shred[MTH / 32];
    int lane = tid & 31, wid = tid >> 5;
    if (lane == 0) shred[wid] = local;
    __syncthreads();
    if (wid == 0) {
        unsigned long long v = (lane < (MTH >> 5)) ? shred[lane] : 0ull;
        v = warpReduceU64(v);
        if (lane == 0) {
            atomicAdd(&g_acc, v);
            __threadfence();
            unsigned old = atomicAdd(&g_done, 1u);
            if (old == BB * MSLICES - 1) {            // last block finalizes
                g_done = 0;                           // self-reset for graph replay
                unsigned long long total = *(volatile unsigned long long*)&g_acc;
                const double ds = 1.0 / (double)KBINS;
                out[0] = (float)((double)total * ds * ds / ((double)BB * (double)HWN));
            }
        }
    }
}

// ---------------------------------------------------------------------------
extern "C" void kernel_launch(void* const* d_in, const int* in_sizes, int n_in,
                              void* d_out, int out_size) {
    const float* x = (const float*)d_in[0];   // [16, 2, 768, 768]
    const float* t = (const float*)d_in[1];   // [16, 768, 768]
    float* out = (float*)d_out;               // scalar

    void* cnt_ptr = nullptr;
    cudaGetSymbolAddress(&cnt_ptr, g_cnt);
    cudaMemsetAsync(cnt_ptr, 0, sizeof(unsigned int) * 2 * BB * KBINS, 0);

    hist_kernel<<<dim3(HBLK, BB), HTH>>>(x, t);
    scan_rows<<<dim3(BB, 2), 1024>>>();
    merge_kernel<<<dim3(MSLICES, BB), MTH>>>(out);
}

// round 16
// speedup vs baseline: 1.4093x; 1.0104x over previous
#include <cuda_runtime.h>
#include <math.h>

#define BB      16
#define HWN     589824            // 768*768
#define KBINS   2048              // 2^11 bins; counters = 256 KB, L2-resident
#define KH      (KBINS / 2)       // packed u16-pair words per histogram
#define HBLK    36                // hist blocks per sample
#define HTH     512
#define EPB     (HWN / HBLK)      // 16384 elements per block (u16-safe)
#define HITER   (EPB / (HTH * 4)) // 8 float4 iterations per thread
#define EVENTS  (2 * KBINS)       // merged CDF events per sample (4096)
#define MTH     512
#define MEPT    2
#define MSLICES (EVENTS / (MTH * MEPT))   // 4 merge blocks per sample -> 64 total

// Scratch (allocation-free rule: __device__ globals)
__device__ unsigned int       g_cnt[2][BB][KBINS];   // hist -> CDF in place
__device__ unsigned long long g_acc;
__device__ unsigned int       g_done = 0;

// ---------------------------------------------------------------------------
// 1) sigmoid(x1-x0) + SMEM-privatized histograms (u16-packed), flush as u64 REDs
// ---------------------------------------------------------------------------
__global__ void __launch_bounds__(HTH, 4)
hist_kernel(const float* __restrict__ x, const float* __restrict__ t) {
    __shared__ unsigned int sp[KH];
    __shared__ unsigned int sq[KH];

    const int tid = threadIdx.x;
    const int b   = blockIdx.y;

    if (blockIdx.x == 0 && b == 0 && tid == 0) g_acc = 0ull;

    for (int i = tid; i < KH; i += HTH) { sp[i] = 0u; sq[i] = 0u; }
    __syncthreads();

    const size_t off = (size_t)blockIdx.x * EPB;
    const float* __restrict__ x0p = x + (size_t)b * 2 * HWN + off;
    const float* __restrict__ x1p = x0p + HWN;
    const float* __restrict__ tp  = t + (size_t)b * HWN + off;
    const float kf = (float)KBINS;

    #pragma unroll
    for (int it = 0; it < HITER; ++it) {
        int i4 = (it * HTH + tid) * 4;
        float4 a0 = *reinterpret_cast<const float4*>(&x0p[i4]);
        float4 a1 = *reinterpret_cast<const float4*>(&x1p[i4]);
        float4 tv = *reinterpret_cast<const float4*>(&tp[i4]);
        #pragma unroll
        for (int j = 0; j < 4; ++j) {
            float d  = (j == 0 ? a0.x - a1.x : j == 1 ? a0.y - a1.y : j == 2 ? a0.z - a1.z : a0.w - a1.w);
            float v  = __fdividef(1.0f, 1.0f + __expf(d));
            int bp = (int)(v * kf);
            bp = bp > KBINS - 1 ? KBINS - 1 : bp;            // sigmoid > 0: no lower clamp
            atomicAdd(&sp[bp >> 1], 1u << ((bp & 1) << 4));
            float tj = (j == 0 ? tv.x : j == 1 ? tv.y : j == 2 ? tv.z : tv.w);
            int bq = (int)(tj * kf);
            bq = bq > KBINS - 1 ? KBINS - 1 : bq;            // t >= 0: no lower clamp
            atomicAdd(&sq[bq >> 1], 1u << ((bq & 1) << 4));
        }
    }
    __syncthreads();

    unsigned long long* __restrict__ gp = reinterpret_cast<unsigned long long*>(&g_cnt[0][b][0]);
    unsigned long long* __restrict__ gq = reinterpret_cast<unsigned long long*>(&g_cnt[1][b][0]);
    for (int w = tid; w < KH; w += HTH) {
        unsigned v = sp[w];
        if (v) atomicAdd(&gp[w], (unsigned long long)(v & 0xFFFFu) |
                                 ((unsigned long long)(v >> 16) << 32));
        v = sq[w];
        if (v) atomicAdd(&gq[w], (unsigned long long)(v & 0xFFFFu) |
                                 ((unsigned long long)(v >> 16) << 32));
    }
}

// ---------------------------------------------------------------------------
// 2) one block scans one (array, sample) row of 2048 counters in place (L2)
// ---------------------------------------------------------------------------
__global__ void scan_rows() {
    __shared__ unsigned int warpsums[32];
    unsigned int* row = &g_cnt[blockIdx.y][blockIdx.x][0];
    int tbase = threadIdx.x * 4;

    uint4 v0 = *reinterpret_cast<uint4*>(&row[tbase]);
    v0.y += v0.x; v0.z += v0.y; v0.w += v0.z;
    unsigned tot = v0.w;

    unsigned lane = threadIdx.x & 31, wid = threadIdx.x >> 5;
    unsigned s = tot;
    #pragma unroll
    for (int o = 1; o < 32; o <<= 1) {
        unsigned n = __shfl_up_sync(0xFFFFFFFFu, s, o);
        if (lane >= o) s += n;
    }
    if (lane == 31) warpsums[wid] = s;
    __syncthreads();
    if (wid == 0) {
        unsigned ws = (lane < 16) ? warpsums[lane] : 0u;
        #pragma unroll
        for (int o = 1; o < 32; o <<= 1) {
            unsigned n = __shfl_up_sync(0xFFFFFFFFu, ws, o);
            if (lane >= o) ws += n;
        }
        warpsums[lane] = ws;
    }
    __syncthreads();

    unsigned prefix = (s - tot) + (wid ? warpsums[wid - 1] : 0u);
    v0.x += prefix; v0.y += prefix; v0.z += prefix; v0.w += prefix;
    *reinterpret_cast<uint4*>(&row[tbase]) = v0;
}

// ---------------------------------------------------------------------------
// 3) merged-event sum straight from L2-resident CDFs + ticket finalize
// ---------------------------------------------------------------------------
__device__ __forceinline__ unsigned long long warpReduceU64(unsigned long long v) {
    #pragma unroll
    for (int o = 16; o > 0; o >>= 1) v += __shfl_down_sync(0xFFFFFFFFu, v, o);
    return v;
}

__global__ void __launch_bounds__(MTH)
merge_kernel(float* __restrict__ out) {
    const int b   = blockIdx.y;
    const int tid = threadIdx.x;
    const unsigned* __restrict__ sp = g_cnt[0][b];
    const unsigned* __restrict__ sq = g_cnt[1][b];

    const int i0 = (blockIdx.x * MTH + tid) * MEPT;

    // merge-path diagonal search: smallest a with (b==0 || a==KBINS || sq[b-1] < sp[a])
    int lo = i0 - KBINS; lo = lo < 0 ? 0 : lo;
    int hi = i0 < KBINS ? i0 : KBINS;
    while (lo < hi) {
        int a = (lo + hi) >> 1;
        int bq = i0 - a;
        if (bq > 0 && a < KBINS && __ldg(&sq[bq - 1]) >= __ldg(&sp[a])) lo = a + 1;
        else hi = a;
    }
    int a = lo, bq = i0 - lo;

    unsigned long long local = 0ull;
    #pragma unroll
    for (int e = 0; e < MEPT; ++e) {
        unsigned vp = (a  < KBINS) ? __ldg(&sp[a])  : 0xFFFFFFFFu;
        unsigned vq = (bq < KBINS) ? __ldg(&sq[bq]) : 0xFFFFFFFFu;
        unsigned vcur;
        if (vp <= vq) { vcur = vp; ++a; } else { vcur = vq; ++bq; }
        unsigned np = (a  < KBINS) ? __ldg(&sp[a])  : 0xFFFFFFFFu;
        unsigned nq = (bq < KBINS) ? __ldg(&sq[bq]) : 0xFFFFFFFFu;
        unsigned vnext = np < nq ? np : nq;
        if (vnext != 0xFFFFFFFFu) {
            int dk = a - bq;
            local += (unsigned long long)(vnext - vcur) * (unsigned long long)(dk * dk);
        }
    }

    local = warpReduceU64(local);
    __shared__ unsigned long long shred[MTH / 32];
    int lane = tid & 31, wid = tid >> 5;
    if (lane == 0) shred[wid] = local;
    __syncthreads();
    if (wid == 0) {
        unsigned long long v = (lane < (MTH >> 5)) ? shred[lane] : 0ull;
        v = warpReduceU64(v);
        if (lane == 0) {
            atomicAdd(&g_acc, v);
            __threadfence();
            unsigned old = atomicAdd(&g_done, 1u);
            if (old == BB * MSLICES - 1) {            // last block finalizes
                g_done = 0;                           // self-reset for graph replay
                unsigned long long total = *(volatile unsigned long long*)&g_acc;
                const double ds = 1.0 / (double)KBINS;
                out[0] = (float)((double)total * ds * ds / ((double)BB * (double)HWN));
            }
        }
    }
}

// ---------------------------------------------------------------------------
extern "C" void kernel_launch(void* const* d_in, const int* in_sizes, int n_in,
                              void* d_out, int out_size) {
    const float* x = (const float*)d_in[0];   // [16, 2, 768, 768]
    const float* t = (const float*)d_in[1];   // [16, 768, 768]
    float* out = (float*)d_out;               // scalar

    void* cnt_ptr = nullptr;
    cudaGetSymbolAddress(&cnt_ptr, g_cnt);
    cudaMemsetAsync(cnt_ptr, 0, sizeof(unsigned int) * 2 * BB * KBINS, 0);

    hist_kernel<<<dim3(HBLK, BB), HTH>>>(x, t);
    scan_rows<<<dim3(BB, 2), 512>>>();
    merge_kernel<<<dim3(MSLICES, BB), MTH>>>(out);
}

// round 17
// speedup vs baseline: 1.4799x; 1.0501x over previous
#include <cuda_runtime.h>
#include <math.h>

#define BB      16
#define HWN     589824            // 768*768
#define KBINS   2048              // 2^11 bins; counters = 256 KB, L2-resident
#define KH      (KBINS / 2)       // packed u16-pair words per histogram
#define HBLK    36                // hist blocks per sample
#define HTH     512
#define EPB     (HWN / HBLK)      // 16384 elements per block (u16-safe)
#define HITER   (EPB / (HTH * 4)) // 8 float4 iterations per thread
#define EVENTS  (2 * KBINS)       // merged CDF events per sample (4096)
#define EPT     (EVENTS / HTH)    // 8 events per thread in the final phase

// Scratch (allocation-free rule: __device__ globals).
// g_cnt starts zeroed (static init); the per-sample final block re-zeroes the
// rows it consumes, so the pipeline is self-cleaning across graph replays.
__device__ unsigned int       g_cnt[2][BB][KBINS];
__device__ unsigned long long g_acc_s[BB];           // per-sample totals (plain stores)
__device__ unsigned int       g_done_s[BB];          // per-sample hist tickets
__device__ unsigned int       g_done = 0;            // global finalize ticket

__device__ __forceinline__ unsigned long long warpReduceU64(unsigned long long v) {
    #pragma unroll
    for (int o = 16; o > 0; o >>= 1) v += __shfl_down_sync(0xFFFFFFFFu, v, o);
    return v;
}

// Load one 2048-bin row from global (L2, .cg), zero it behind us, and write the
// inclusive scan into smem dst. 512 threads x 4 elements.
__device__ __forceinline__ void scan_row_consume(unsigned* __restrict__ row,
                                                 unsigned* __restrict__ dst,
                                                 unsigned* warpsums, int tid) {
    int tbase = tid * 4;
    uint4 v = __ldcg(reinterpret_cast<const uint4*>(&row[tbase]));
    *reinterpret_cast<uint4*>(&row[tbase]) = make_uint4(0u, 0u, 0u, 0u);  // self-clean

    v.y += v.x; v.z += v.y; v.w += v.z;
    unsigned tot = v.w;

    unsigned lane = tid & 31, wid = tid >> 5;
    unsigned s = tot;
    #pragma unroll
    for (int o = 1; o < 32; o <<= 1) {
        unsigned n = __shfl_up_sync(0xFFFFFFFFu, s, o);
        if (lane >= o) s += n;
    }
    if (lane == 31) warpsums[wid] = s;
    __syncthreads();
    if (wid == 0) {
        unsigned ws = (lane < (HTH >> 5)) ? warpsums[lane] : 0u;
        #pragma unroll
        for (int o = 1; o < 32; o <<= 1) {
            unsigned n = __shfl_up_sync(0xFFFFFFFFu, ws, o);
            if (lane >= o) ws += n;
        }
        warpsums[lane] = ws;
    }
    __syncthreads();

    unsigned prefix = (s - tot) + (wid ? warpsums[wid - 1] : 0u);
    v.x += prefix; v.y += prefix; v.z += prefix; v.w += prefix;
    *reinterpret_cast<uint4*>(&dst[tbase]) = v;
    __syncthreads();
}

// ---------------------------------------------------------------------------
// Single fused kernel: hist -> (last block per sample) scan+merge -> (last
// block overall) finalize. Tickets self-reset; g_cnt left zeroed.
// ---------------------------------------------------------------------------
__global__ void __launch_bounds__(HTH, 4)
wass_kernel(const float* __restrict__ x, const float* __restrict__ t,
            float* __restrict__ out) {
    __shared__ unsigned sh[2 * KBINS];   // hist: sp=sh[0..KH), sq=sh[KH..2KH); final: 2 CDFs
    __shared__ unsigned warpsums[32];
    __shared__ unsigned long long shred[HTH / 32];
    __shared__ int is_final;

    const int tid = threadIdx.x;
    const int b   = blockIdx.y;

    // ---------------- phase 1: histogram ----------------
    unsigned* sp = sh;
    unsigned* sq = sh + KH;
    for (int i = tid; i < KH; i += HTH) { sp[i] = 0u; sq[i] = 0u; }
    __syncthreads();

    const size_t off = (size_t)blockIdx.x * EPB;
    const float* __restrict__ x0p = x + (size_t)b * 2 * HWN + off;
    const float* __restrict__ x1p = x0p + HWN;
    const float* __restrict__ tp  = t + (size_t)b * HWN + off;
    const float kf = (float)KBINS;

    #pragma unroll
    for (int it = 0; it < HITER; ++it) {
        int i4 = (it * HTH + tid) * 4;
        float4 a0 = *reinterpret_cast<const float4*>(&x0p[i4]);
        float4 a1 = *reinterpret_cast<const float4*>(&x1p[i4]);
        float4 tv = *reinterpret_cast<const float4*>(&tp[i4]);
        #pragma unroll
        for (int j = 0; j < 4; ++j) {
            float d  = (j == 0 ? a0.x - a1.x : j == 1 ? a0.y - a1.y : j == 2 ? a0.z - a1.z : a0.w - a1.w);
            float v  = __fdividef(1.0f, 1.0f + __expf(d));
            int bp = (int)(v * kf);
            bp = bp > KBINS - 1 ? KBINS - 1 : bp;            // sigmoid > 0: no lower clamp
            atomicAdd(&sp[bp >> 1], 1u << ((bp & 1) << 4));
            float tj = (j == 0 ? tv.x : j == 1 ? tv.y : j == 2 ? tv.z : tv.w);
            int bq = (int)(tj * kf);
            bq = bq > KBINS - 1 ? KBINS - 1 : bq;            // t >= 0: no lower clamp
            atomicAdd(&sq[bq >> 1], 1u << ((bq & 1) << 4));
        }
    }
    __syncthreads();

    // flush packed u16 pairs as one u64 RED per word (halves never carry)
    unsigned long long* __restrict__ gp = reinterpret_cast<unsigned long long*>(&g_cnt[0][b][0]);
    unsigned long long* __restrict__ gq = reinterpret_cast<unsigned long long*>(&g_cnt[1][b][0]);
    for (int w = tid; w < KH; w += HTH) {
        unsigned v = sp[w];
        if (v) atomicAdd(&gp[w], (unsigned long long)(v & 0xFFFFu) |
                                 ((unsigned long long)(v >> 16) << 32));
        v = sq[w];
        if (v) atomicAdd(&gq[w], (unsigned long long)(v & 0xFFFFu) |
                                 ((unsigned long long)(v >> 16) << 32));
    }

    // ---------------- phase 2: per-sample ticket ----------------
    __syncthreads();
    if (tid == 0) {
        __threadfence();
        unsigned olds = atomicAdd(&g_done_s[b], 1u);
        is_final = (olds == HBLK - 1);
        if (is_final) g_done_s[b] = 0;               // self-reset for graph replay
    }
    __syncthreads();
    if (!is_final) return;

    // ---------------- phase 3 (last block of sample b): scan + merge -------
    unsigned* cp = sh;                // CDF of pred, 2048
    unsigned* cq = sh + KBINS;        // CDF of target, 2048
    scan_row_consume(&g_cnt[0][b][0], cp, warpsums, tid);
    scan_row_consume(&g_cnt[1][b][0], cq, warpsums, tid);

    // merged-event sum: events [tid*EPT, (tid+1)*EPT)
    const int i0 = tid * EPT;
    int lo = i0 - KBINS; lo = lo < 0 ? 0 : lo;
    int hi = i0 < KBINS ? i0 : KBINS;
    while (lo < hi) {
        int a = (lo + hi) >> 1;
        int bq2 = i0 - a;
        if (bq2 > 0 && a < KBINS && cq[bq2 - 1] >= cp[a]) lo = a + 1;
        else hi = a;
    }
    int a = lo, bq2 = i0 - lo;

    unsigned long long local = 0ull;
    #pragma unroll
    for (int e = 0; e < EPT; ++e) {
        unsigned vp = (a   < KBINS) ? cp[a]   : 0xFFFFFFFFu;
        unsigned vq = (bq2 < KBINS) ? cq[bq2] : 0xFFFFFFFFu;
        unsigned vcur;
        if (vp <= vq) { vcur = vp; ++a; } else { vcur = vq; ++bq2; }
        unsigned np = (a   < KBINS) ? cp[a]   : 0xFFFFFFFFu;
        unsigned nq = (bq2 < KBINS) ? cq[bq2] : 0xFFFFFFFFu;
        unsigned vnext = np < nq ? np : nq;
        if (vnext != 0xFFFFFFFFu) {
            int dk = a - bq2;
            local += (unsigned long long)(vnext - vcur) * (unsigned long long)(dk * dk);
        }
    }

    local = warpReduceU64(local);
    int lane = tid & 31, wid = tid >> 5;
    if (lane == 0) shred[wid] = local;
    __syncthreads();
    if (wid == 0) {
        unsigned long long v = (lane < (HTH >> 5)) ? shred[lane] : 0ull;
        v = warpReduceU64(v);
        if (lane == 0) {
            g_acc_s[b] = v;                           // plain store; overwritten each launch
            __threadfence();
            unsigned old = atomicAdd(&g_done, 1u);
            if (old == BB - 1) {                      // last sample finalizes
                g_done = 0;                           // self-reset for graph replay
                unsigned long long total = 0ull;
                #pragma unroll
                for (int i = 0; i < BB; ++i)
                    total += *(volatile unsigned long long*)&g_acc_s[i];
                const double ds = 1.0 / (double)KBINS;
                out[0] = (float)((double)total * ds * ds / ((double)BB * (double)HWN));
            }
        }
    }
}

// ---------------------------------------------------------------------------
extern "C" void kernel_launch(void* const* d_in, const int* in_sizes, int n_in,
                              void* d_out, int out_size) {
    const float* x = (const float*)d_in[0];   // [16, 2, 768, 768]
    const float* t = (const float*)d_in[1];   // [16, 768, 768]
    float* out = (float*)d_out;               // scalar

    wass_kernel<<<dim3(HBLK, BB), HTH>>>(x, t, out);
}